// round 12
// baseline (speedup 1.0000x reference)
#include <cuda_runtime.h>

#define H 8192
#define W 8192
#define KH 7
#define KW 7
#define OH (H - KH + 1)   // 8186
#define OW (W - KW + 1)   // 8186

#define TPB    128
#define RPT    16                    // rows per thread
#define TILE_X 64                    // 32 lanes * 2 cols (one f32x2 pair)
#define TILE_Y 64                    // 4 warps * 16 rows
#define SM_H   (TILE_Y + KH - 1)     // 70
#define SM_W   (TILE_X + KW - 1)     // 70
#define SP     72                    // smem pitch (floats)
#define VLEN   (RPT + KH - 1)        // 22

typedef unsigned long long u64;

__device__ __forceinline__ u64 fma2(u64 a, u64 b, u64 c) {
    u64 d;
    asm("fma.rn.f32x2 %0, %1, %2, %3;" : "=l"(d) : "l"(a), "l"(b), "l"(c));
    return d;
}
__device__ __forceinline__ u64 splat2(float w) {
    u64 d;
    asm("mov.b64 %0, {%1, %1};" : "=l"(d) : "f"(w));
    return d;
}
// {hi(a), lo(b)} — 2 register MOVs
__device__ __forceinline__ u64 crossing(u64 a, u64 b) {
    u64 r;
    asm("{\n\t.reg .b32 al, ah, bl, bh;\n\t"
        "mov.b64 {al, ah}, %1;\n\t"
        "mov.b64 {bl, bh}, %2;\n\t"
        "mov.b64 %0, {ah, bl};\n\t}"
        : "=l"(r) : "l"(a), "l"(b));
    return r;
}

__global__ __launch_bounds__(TPB)
void conv7x7_tx_kernel(const float* __restrict__ x,
                       const float* __restrict__ wgt,
                       const float* __restrict__ bias,
                       float* __restrict__ out)
{
    __shared__ __align__(16) float tile[SM_H * SP];
    __shared__ __align__(16) u64 wpair[KW * KH];   // [kc*7 + kr] = {w,w}

    const int tid  = threadIdx.x;
    const int col0 = blockIdx.x * TILE_X;
    const int row0 = blockIdx.y * TILE_Y;

    if (tid < KH * KW) {
        const int kc = tid / 7;
        const int kr = tid - kc * 7;
        wpair[tid] = splat2(wgt[kr * KW + kc]);
    }

    // ---- Single tile fill, clamped; float2 fast path for interior ----
    if (row0 + SM_H <= H && col0 + SM_W <= W) {
        for (int idx = tid; idx < SM_H * 35; idx += TPB) {
            const int r  = idx / 35;
            const int c2 = idx - r * 35;
            const float2 v = __ldg((const float2*)&x[(size_t)(row0 + r) * W + col0 + 2 * c2]);
            *(float2*)&tile[r * SP + 2 * c2] = v;
        }
    } else {
        for (int idx = tid; idx < SM_H * SM_W; idx += TPB) {
            const int r = idx / SM_W;
            const int c = idx - r * SM_W;
            const int gr = min(row0 + r, H - 1);
            const int gc = min(col0 + c, W - 1);
            tile[r * SP + c] = __ldg(&x[(size_t)gr * W + gc]);
        }
    }
    __syncthreads();

    const int lane  = tid & 31;
    const int rbase = (tid >> 5) * RPT;   // 0,16,32,48
    const int cb    = lane * 2;           // 0..62 (u64-aligned)

    u64 acc[RPT];
#pragma unroll
    for (int o = 0; o < RPT; o++) acc[o] = 0ULL;

    const float* base = &tile[rbase * SP + cb];

    // ---- Step 0: kc = 0 (7 weight pairs live; window value dies per t) ----
    {
        u64 w0[KH];
#pragma unroll
        for (int kr = 0; kr < KH; kr++) w0[kr] = wpair[kr];
#pragma unroll
        for (int t = 0; t < VLEN; t++) {
            const u64 B = *(const u64*)(base + t * SP);
#pragma unroll
            for (int kr = 0; kr < KH; kr++) {
                const int o = t - kr;
                if (o >= 0 && o < RPT) acc[o] = fma2(B, w0[kr], acc[o]);
            }
        }
    }

    // ---- Steps s=1..3: kc = {2s-1, 2s}; per-t transient A,B,X only ----
#pragma unroll
    for (int s = 1; s <= 3; s++) {
        u64 wo[KH], we[KH];                // 14 pairs live (proven safe)
#pragma unroll
        for (int kr = 0; kr < KH; kr++) {
            wo[kr] = wpair[(2 * s - 1) * 7 + kr];
            we[kr] = wpair[(2 * s) * 7 + kr];
        }
#pragma unroll
        for (int t = 0; t < VLEN; t++) {
            const float* pt = base + t * SP;
            const u64 A = *(const u64*)(pt + 2 * s - 2);   // cols {2s-2, 2s-1}
            const u64 B = *(const u64*)(pt + 2 * s);       // cols {2s,   2s+1}
            const u64 X = crossing(A, B);                  // cols {2s-1, 2s}
#pragma unroll
            for (int kr = 0; kr < KH; kr++) {
                const int o = t - kr;                      // compile-time per (t,kr)
                if (o >= 0 && o < RPT) {
                    u64 a = acc[o];
                    a = fma2(X, wo[kr], a);
                    a = fma2(B, we[kr], a);
                    acc[o] = a;
                }
            }
        }
    }

    // ---- Epilogue: bias + STG.64 (OW even: pairs never straddle) ----
    const u64 b2 = splat2(__ldg(&bias[0]));
    const int ocol = col0 + cb;
    if (ocol < OW) {
#pragma unroll
        for (int o = 0; o < RPT; o++) {
            const int orow = row0 + rbase + o;
            if (orow < OH) {
                u64 r;
                asm("add.rn.f32x2 %0, %1, %2;" : "=l"(r) : "l"(acc[o]), "l"(b2));
                *(u64*)&out[(size_t)orow * OW + ocol] = r;
            }
        }
    }
}

extern "C" void kernel_launch(void* const* d_in, const int* in_sizes, int n_in,
                              void* d_out, int out_size)
{
    const float* x    = (const float*)d_in[0];
    const float* wgt  = (const float*)d_in[1];
    const float* bias = (const float*)d_in[2];
    float* out        = (float*)d_out;

    dim3 block(TPB, 1, 1);
    dim3 grid((OW + TILE_X - 1) / TILE_X, (OH + TILE_Y - 1) / TILE_Y, 1);
    conv7x7_tx_kernel<<<grid, block>>>(x, wgt, bias, out);
}

// round 13
// speedup vs baseline: 1.8111x; 1.8111x over previous
#include <cuda_runtime.h>

#define H 8192
#define W 8192
#define KH 7
#define KW 7
#define OH (H - KH + 1)   // 8186
#define OW (W - KW + 1)   // 8186

#define TILE_X 64          // 32 lanes * 2 cols (one f32x2 pair)
#define TILE_Y 48          // 4 warps * 12 rows
#define TPB   128
#define RPT   12           // rows per thread
#define SM_H  (TILE_Y + KH - 1)   // 54
#define SM_W  (TILE_X + KW - 1)   // 70
#define SP    72                  // smem row pitch (floats)
#define VLEN  (RPT + KH - 1)      // 18

typedef unsigned long long u64;

__device__ __forceinline__ u64 fma2(u64 a, u64 b, u64 c) {
    u64 d;
    asm("fma.rn.f32x2 %0, %1, %2, %3;" : "=l"(d) : "l"(a), "l"(b), "l"(c));
    return d;
}
__device__ __forceinline__ u64 splat2(float w) {
    u64 d;
    asm("mov.b64 %0, {%1, %1};" : "=l"(d) : "f"(w));
    return d;
}

__global__ __launch_bounds__(TPB)
void conv7x7_r12_kernel(const float* __restrict__ x,
                        const float* __restrict__ wgt,
                        const float* __restrict__ bias,
                        float* __restrict__ out)
{
    __shared__ __align__(16) float smA[SM_H * SP];   // tile
    __shared__ __align__(16) float smB[SM_H * SP];   // tile shifted left 1 col
    __shared__ __align__(16) u64 wpair[KW * KH];     // [kc*7+kr] = {w,w}

    const int tid  = threadIdx.x;
    const int col0 = blockIdx.x * TILE_X;
    const int row0 = blockIdx.y * TILE_Y;

    if (tid < KH * KW) {
        const int kc = tid / 7;
        const int kr = tid - kc * 7;
        wpair[tid] = splat2(wgt[kr * KW + kc]);
    }

    // ---- Tile fill (R3-proven): clamped reads, division-free main region ----
    // Main: cols 0..63, 128 threads = 64 cols x 2 row phases.
    {
        const int c   = tid & 63;
        const int rph = tid >> 6;
        const int gc  = min(col0 + c, W - 1);
#pragma unroll
        for (int r = 0; r < SM_H; r += 2) {
            const int rr = r + rph;                    // 0..53
            const int gr = min(row0 + rr, H - 1);
            const float v = __ldg(&x[(size_t)gr * W + gc]);
            smA[rr * SP + c] = v;
            if (c > 0) smB[rr * SP + c - 1] = v;
        }
    }
    // Halo: cols 64..69, 54 rows x 6 cols = 324 elems.
#pragma unroll
    for (int k = 0; k < 3; k++) {
        const int idx = tid + k * TPB;                 // 0..383
        if (idx < SM_H * 6) {
            const int rr = idx / 6;
            const int c  = 64 + (idx - rr * 6);        // 64..69
            const int gr = min(row0 + rr, H - 1);
            const int gc = min(col0 + c, W - 1);
            const float v = __ldg(&x[(size_t)gr * W + gc]);
            smA[rr * SP + c] = v;
            smB[rr * SP + c - 1] = v;                  // 63..68
        }
    }
    __syncthreads();

    // ---- Compute: 2 cols x 12 rows per thread, batch loads per kc step ----
    const int tx    = tid & 31;
    const int rbase = (tid >> 5) * RPT;                // 0,12,24,36
    const int cb    = tx * 2;                          // 0..62

    u64 acc[RPT];
#pragma unroll
    for (int o = 0; o < RPT; o++) acc[o] = 0ULL;

    const float* baseA = &smA[rbase * SP + cb];
    const float* baseB = &smB[rbase * SP + cb];

#pragma unroll
    for (int kc = 0; kc < KW; kc++) {
        const float* p = (kc & 1) ? (baseB + (kc - 1)) : (baseA + kc);

        u64 w2[KH];
#pragma unroll
        for (int kr = 0; kr < KH; kr++) w2[kr] = wpair[kc * 7 + kr];

        u64 v[VLEN];
#pragma unroll
        for (int t = 0; t < VLEN; t++)
            v[t] = *(const u64*)(p + t * SP);          // aligned LDS.64, batched

#pragma unroll
        for (int kr = 0; kr < KH; kr++)
#pragma unroll
            for (int o = 0; o < RPT; o++)
                acc[o] = fma2(v[kr + o], w2[kr], acc[o]);
    }

    // ---- Epilogue: bias add + STG.64 (OW even: pairs never straddle) ----
    const u64 b2 = splat2(__ldg(&bias[0]));
    const int ocol = col0 + cb;
    if (ocol < OW) {
#pragma unroll
        for (int o = 0; o < RPT; o++) {
            const int orow = row0 + rbase + o;
            if (orow < OH) {
                u64 r;
                asm("add.rn.f32x2 %0, %1, %2;" : "=l"(r) : "l"(acc[o]), "l"(b2));
                *(u64*)&out[(size_t)orow * OW + ocol] = r;
            }
        }
    }
}

extern "C" void kernel_launch(void* const* d_in, const int* in_sizes, int n_in,
                              void* d_out, int out_size)
{
    const float* x    = (const float*)d_in[0];
    const float* wgt  = (const float*)d_in[1];
    const float* bias = (const float*)d_in[2];
    float* out        = (float*)d_out;

    dim3 block(TPB, 1, 1);
    dim3 grid((OW + TILE_X - 1) / TILE_X, (OH + TILE_Y - 1) / TILE_Y, 1);
    conv7x7_r12_kernel<<<grid, block>>>(x, wgt, bias, out);
}